// round 1
// baseline (speedup 1.0000x reference)
#include <cuda_runtime.h>

#define F        128
#define NRBF     20
#define TM       64
#define NTHREADS 256
#define SROW     132
// smem floats: s 64*132=8448 ; overlay 24576 ; w 24576 ; rn 192 ; idx 64
#define SMEM_FLOATS (8448 + 24576 + 24576 + 192 + 64)
#define SMEM_BYTES  (SMEM_FLOATS * 4)

__device__ float g_sum;

static __device__ __forceinline__ unsigned long long pack2(float x){
  unsigned long long u;
  asm("mov.b64 %0, {%1, %1};" : "=l"(u) : "f"(x));
  return u;
}
static __device__ __forceinline__ unsigned long long pack2f(float lo, float hi){
  unsigned long long u;
  asm("mov.b64 %0, {%1, %2};" : "=l"(u) : "f"(lo), "f"(hi));
  return u;
}
static __device__ __forceinline__ unsigned long long ffma2(unsigned long long a,
    unsigned long long b, unsigned long long c){
  unsigned long long d;
  asm("fma.rn.f32x2 %0, %1, %2, %3;" : "=l"(d) : "l"(a), "l"(b), "l"(c));
  return d;
}
static __device__ __forceinline__ void unpack2(unsigned long long u, float& lo, float& hi){
  asm("mov.b64 {%0, %1}, %2;" : "=f"(lo), "=f"(hi) : "l"(u));
}
static __device__ __forceinline__ void red4(float* p, float a, float b, float c, float d){
  asm volatile("red.global.add.v4.f32 [%0], {%1, %2, %3, %4};"
               :: "l"(p), "f"(a), "f"(b), "f"(c), "f"(d) : "memory");
}

__global__ void zero_gsum_kernel(){ g_sum = 0.f; }

__global__ void reduce_sumsq_kernel(const float* __restrict__ r, int n){
  float s = 0.f;
  for (int i = blockIdx.x * blockDim.x + threadIdx.x; i < n; i += gridDim.x * blockDim.x){
    float x = r[i];
    s = fmaf(x, x, s);
  }
  #pragma unroll
  for (int o = 16; o > 0; o >>= 1) s += __shfl_xor_sync(0xffffffffu, s, o);
  __shared__ float ws[8];
  int lane = threadIdx.x & 31, w = threadIdx.x >> 5;
  if (lane == 0) ws[w] = s;
  __syncthreads();
  if (threadIdx.x < 32){
    s = (threadIdx.x < 8) ? ws[threadIdx.x] : 0.f;
    #pragma unroll
    for (int o = 4; o > 0; o >>= 1) s += __shfl_xor_sync(0xffffffffu, s, o);
    if (threadIdx.x == 0) atomicAdd(&g_sum, s);
  }
}

__global__ void __launch_bounds__(NTHREADS, 1)
fused_message_kernel(
    const float* __restrict__ s_g, const float* __restrict__ r_g,
    const float* __restrict__ v_g, const int*   __restrict__ idx_g,
    const float* __restrict__ Wp_g, const float* __restrict__ bphi_g,
    const float* __restrict__ Ww_g, const float* __restrict__ bw_g,
    float* __restrict__ out_v, float* __restrict__ out_s, int E)
{
  extern __shared__ float sm[];
  float* s_sm  = sm;                   // [64][SROW]
  float* ov_sm = sm + TM*SROW;         // overlay: prologue rbf+Ww, mainloop W_phi half [64][384]
  float* w_sm  = ov_sm + 24576;        // [64][384]
  float* rn_sm = w_sm + 24576;         // [64][3]
  int*  idx_sm = (int*)(rn_sm + TM*3); // [64]

  const int tid = threadIdx.x;
  const int tx  = tid & 15;   // feature group: owns n = {tx*4..+3} and {64+tx*4..+3} per chunk
  const int ty  = tid >> 4;   // edge group:    owns edges ty*4..ty*4+3
  const int eb  = blockIdx.x * TM;

  float* rbfO = ov_sm;             // [64][NRBF]
  float* WwO  = ov_sm + TM*NRBF;   // [20][384]

  // ---------------- prologue: rbf / rn / idx / Ww / s tile ----------------
  if (tid < TM){
    int e = eb + tid;
    if (e < E){
      float rx = r_g[3*e+0], ry = r_g[3*e+1], rz = r_g[3*e+2];
      float rn = sqrtf(fmaf(rx,rx, fmaf(ry,ry, rz*rz)));
      float invg = rsqrtf(g_sum);                 // global Frobenius norm of r
      rn_sm[tid*3+0] = rx*invg;
      rn_sm[tid*3+1] = ry*invg;
      rn_sm[tid*3+2] = rz*invg;
      idx_sm[tid] = idx_g[e];
      float inv_rn = 1.f/rn;
      const float c0 = 0.62831853071795864769f;   // pi / R_CUT
      #pragma unroll
      for (int k = 0; k < NRBF; k++){
        float t = sinf((float)(k+1) * c0 * rn) * inv_rn;
        rbfO[tid*NRBF + k] = (t <= 5.0f) ? 0.5f*(cosf(c0*t) + 1.f) : 0.f;
      }
    } else {
      rn_sm[tid*3+0]=0.f; rn_sm[tid*3+1]=0.f; rn_sm[tid*3+2]=0.f;
      idx_sm[tid]=0;
      #pragma unroll
      for (int k = 0; k < NRBF; k++) rbfO[tid*NRBF+k] = 0.f;
    }
  }
  for (int i = tid; i < NRBF*3*F; i += NTHREADS) WwO[i] = Ww_g[i];
  {
    const int lane = tid & 31, wrp = tid >> 5;
    const float4* s4 = (const float4*)s_g;
    #pragma unroll
    for (int j = 0; j < 8; j++){
      int el = wrp*8 + j;
      int e  = eb + el;
      float4 val = make_float4(0.f,0.f,0.f,0.f);
      if (e < E) val = s4[(size_t)e*(F/4) + lane];
      *((float4*)(s_sm + el*SROW) + lane) = val;
    }
  }
  __syncthreads();

  // ---------------- w tile: w = rbf @ W_w + b_w  (packed f32x2) ----------------
  {
    #pragma unroll
    for (int c = 0; c < 3; c++){
      unsigned long long wacc[4][2][2];
      {
        const float4 b0 = *(const float4*)(bw_g + c*F + tx*4);
        const float4 b1 = *(const float4*)(bw_g + c*F + 64 + tx*4);
        unsigned long long i00 = pack2f(b0.x,b0.y), i01 = pack2f(b0.z,b0.w);
        unsigned long long i10 = pack2f(b1.x,b1.y), i11 = pack2f(b1.z,b1.w);
        #pragma unroll
        for (int i = 0; i < 4; i++){
          wacc[i][0][0]=i00; wacc[i][0][1]=i01; wacc[i][1][0]=i10; wacc[i][1][1]=i11;
        }
      }
      #pragma unroll
      for (int k = 0; k < NRBF; k++){
        unsigned long long rb[4];
        #pragma unroll
        for (int i = 0; i < 4; i++) rb[i] = pack2(rbfO[(ty*4+i)*NRBF + k]);
        const ulonglong2 g0 = *(const ulonglong2*)(WwO + k*3*F + c*F + tx*4);
        const ulonglong2 g1 = *(const ulonglong2*)(WwO + k*3*F + c*F + 64 + tx*4);
        #pragma unroll
        for (int i = 0; i < 4; i++){
          wacc[i][0][0] = ffma2(rb[i], g0.x, wacc[i][0][0]);
          wacc[i][0][1] = ffma2(rb[i], g0.y, wacc[i][0][1]);
          wacc[i][1][0] = ffma2(rb[i], g1.x, wacc[i][1][0]);
          wacc[i][1][1] = ffma2(rb[i], g1.y, wacc[i][1][1]);
        }
      }
      #pragma unroll
      for (int i = 0; i < 4; i++){
        ulonglong2 st0; st0.x = wacc[i][0][0]; st0.y = wacc[i][0][1];
        ulonglong2 st1; st1.x = wacc[i][1][0]; st1.y = wacc[i][1][1];
        *(ulonglong2*)(w_sm + (ty*4+i)*3*F + c*F + tx*4)      = st0;
        *(ulonglong2*)(w_sm + (ty*4+i)*3*F + c*F + 64 + tx*4) = st1;
      }
    }
  }
  __syncthreads();

  // ---------------- GEMM: phi = s @ W_phi (packed f32x2, W staged in 2 halves) ----------------
  unsigned long long acc[3][4][2][2];
  #pragma unroll
  for (int c = 0; c < 3; c++)
    #pragma unroll
    for (int i = 0; i < 4; i++)
      #pragma unroll
      for (int q = 0; q < 2; q++){ acc[c][i][q][0] = 0ULL; acc[c][i][q][1] = 0ULL; }

  #pragma unroll 1
  for (int h = 0; h < 2; h++){
    {
      const float4* W4  = (const float4*)(Wp_g + h*64*3*F);
      float4*       ov4 = (float4*)ov_sm;
      #pragma unroll
      for (int i = 0; i < 24; i++)       // 24*256*4 = 24576 floats
        ov4[i*NTHREADS + tid] = W4[i*NTHREADS + tid];
    }
    __syncthreads();
    #pragma unroll 2
    for (int kk = 0; kk < 64; kk++){
      const int k = h*64 + kk;
      unsigned long long A[4];
      #pragma unroll
      for (int i = 0; i < 4; i++) A[i] = pack2(s_sm[(ty*4+i)*SROW + k]);
      #pragma unroll
      for (int c = 0; c < 3; c++){
        const ulonglong2 g0 = *(const ulonglong2*)(ov_sm + kk*3*F + c*F + tx*4);
        const ulonglong2 g1 = *(const ulonglong2*)(ov_sm + kk*3*F + c*F + 64 + tx*4);
        #pragma unroll
        for (int i = 0; i < 4; i++){
          acc[c][i][0][0] = ffma2(A[i], g0.x, acc[c][i][0][0]);
          acc[c][i][0][1] = ffma2(A[i], g0.y, acc[c][i][0][1]);
          acc[c][i][1][0] = ffma2(A[i], g1.x, acc[c][i][1][0]);
          acc[c][i][1][1] = ffma2(A[i], g1.y, acc[c][i][1][1]);
        }
      }
    }
    __syncthreads();
  }

  // ---------------- epilogue: gate + vectorized reductions ----------------
  float4 bph[3][2];
  #pragma unroll
  for (int c = 0; c < 3; c++){
    bph[c][0] = *(const float4*)(bphi_g + c*F + tx*4);
    bph[c][1] = *(const float4*)(bphi_g + c*F + 64 + tx*4);
  }

  #pragma unroll
  for (int i = 0; i < 4; i++){
    const int el = ty*4 + i;
    const int e  = eb + el;
    if (e < E){
      const int node = idx_sm[el];
      const float rn0 = rn_sm[el*3+0], rn1 = rn_sm[el*3+1], rn2 = rn_sm[el*3+2];
      float sv[2][4], ssv[2][4], sr[2][4];
      #pragma unroll
      for (int c = 0; c < 3; c++){
        #pragma unroll
        for (int q = 0; q < 2; q++){
          const float4 wq = *(const float4*)(w_sm + el*3*F + c*F + q*64 + tx*4);
          float lo0, hi0, lo1, hi1;
          unpack2(acc[c][i][q][0], lo0, hi0);
          unpack2(acc[c][i][q][1], lo1, hi1);
          const float4 bq = bph[c][q];
          float o0 = wq.x * (lo0 + bq.x);
          float o1 = wq.y * (hi0 + bq.y);
          float o2 = wq.z * (lo1 + bq.z);
          float o3 = wq.w * (hi1 + bq.w);
          float* dst = (c==0) ? sv[q] : (c==1) ? ssv[q] : sr[q];
          dst[0]=o0; dst[1]=o1; dst[2]=o2; dst[3]=o3;
        }
      }
      // out_s += ss
      float* osp = out_s + (size_t)node*F + tx*4;
      red4(osp,      ssv[0][0], ssv[0][1], ssv[0][2], ssv[0][3]);
      red4(osp + 64, ssv[1][0], ssv[1][1], ssv[1][2], ssv[1][3]);
      // out_v += sv*v + sr*rn[d]
      const float* vp  = v_g  + (size_t)e*3*F    + tx*4;
      float*       ovp = out_v + (size_t)node*3*F + tx*4;
      #pragma unroll
      for (int d = 0; d < 3; d++){
        const float rnd = (d==0) ? rn0 : (d==1) ? rn1 : rn2;
        #pragma unroll
        for (int q = 0; q < 2; q++){
          const float4 vv = *(const float4*)(vp + d*F + q*64);
          float m0 = fmaf(sv[q][0], vv.x, sr[q][0]*rnd);
          float m1 = fmaf(sv[q][1], vv.y, sr[q][1]*rnd);
          float m2 = fmaf(sv[q][2], vv.z, sr[q][2]*rnd);
          float m3 = fmaf(sv[q][3], vv.w, sr[q][3]*rnd);
          red4(ovp + d*F + q*64, m0, m1, m2, m3);
        }
      }
    }
  }
}

extern "C" void kernel_launch(void* const* d_in, const int* in_sizes, int n_in,
                              void* d_out, int out_size){
  const float* s_g  = (const float*)d_in[0];
  const float* r_g  = (const float*)d_in[1];
  const float* v_g  = (const float*)d_in[2];
  const int*   idx  = (const int*)  d_in[3];
  const float* Wp   = (const float*)d_in[4];
  const float* bphi = (const float*)d_in[5];
  const float* Ww   = (const float*)d_in[6];
  const float* bw   = (const float*)d_in[7];
  const int E = in_sizes[1] / 3;            // r is (E,3)
  const int N = out_size / (4*F);           // out = out_v (N*3*F) ++ out_s (N*F)
  float* out_v = (float*)d_out;
  float* out_s = out_v + (size_t)N*3*F;

  cudaMemsetAsync(d_out, 0, (size_t)out_size * sizeof(float));
  zero_gsum_kernel<<<1,1>>>();
  reduce_sumsq_kernel<<<512, 256>>>(r_g, 3*E);
  cudaFuncSetAttribute(fused_message_kernel,
                       cudaFuncAttributeMaxDynamicSharedMemorySize, SMEM_BYTES);
  const int blocks = (E + TM - 1) / TM;
  fused_message_kernel<<<blocks, NTHREADS, SMEM_BYTES>>>(
      s_g, r_g, v_g, idx, Wp, bphi, Ww, bw, out_v, out_s, E);
}

// round 2
// speedup vs baseline: 1.0053x; 1.0053x over previous
#include <cuda_runtime.h>

#define F        128
#define NRBF     20
#define TM       64
#define NTHREADS 256
#define SROW     132
// smem floats: s 64*132=8448 ; overlay 24576 ; w 24576 ; rn 192 ; idx 64
#define SMEM_FLOATS (8448 + 24576 + 24576 + 192 + 64)
#define SMEM_BYTES  (SMEM_FLOATS * 4)

__device__ float g_sum;

static __device__ __forceinline__ unsigned long long pack2(float x){
  unsigned long long u;
  asm("mov.b64 %0, {%1, %1};" : "=l"(u) : "f"(x));
  return u;
}
static __device__ __forceinline__ unsigned long long pack2f(float lo, float hi){
  unsigned long long u;
  asm("mov.b64 %0, {%1, %2};" : "=l"(u) : "f"(lo), "f"(hi));
  return u;
}
static __device__ __forceinline__ unsigned long long ffma2(unsigned long long a,
    unsigned long long b, unsigned long long c){
  unsigned long long d;
  asm("fma.rn.f32x2 %0, %1, %2, %3;" : "=l"(d) : "l"(a), "l"(b), "l"(c));
  return d;
}
static __device__ __forceinline__ void unpack2(unsigned long long u, float& lo, float& hi){
  asm("mov.b64 {%0, %1}, %2;" : "=f"(lo), "=f"(hi) : "l"(u));
}
static __device__ __forceinline__ void red4(float* p, float a, float b, float c, float d){
  asm volatile("red.global.add.v4.f32 [%0], {%1, %2, %3, %4};"
               :: "l"(p), "f"(a), "f"(b), "f"(c), "f"(d) : "memory");
}

__global__ void zero_gsum_kernel(){ g_sum = 0.f; }

__global__ void reduce_sumsq_kernel(const float* __restrict__ r, int n){
  float s = 0.f;
  for (int i = blockIdx.x * blockDim.x + threadIdx.x; i < n; i += gridDim.x * blockDim.x){
    float x = r[i];
    s = fmaf(x, x, s);
  }
  #pragma unroll
  for (int o = 16; o > 0; o >>= 1) s += __shfl_xor_sync(0xffffffffu, s, o);
  __shared__ float ws[8];
  int lane = threadIdx.x & 31, w = threadIdx.x >> 5;
  if (lane == 0) ws[w] = s;
  __syncthreads();
  if (threadIdx.x < 32){
    s = (threadIdx.x < 8) ? ws[threadIdx.x] : 0.f;
    #pragma unroll
    for (int o = 4; o > 0; o >>= 1) s += __shfl_xor_sync(0xffffffffu, s, o);
    if (threadIdx.x == 0) atomicAdd(&g_sum, s);
  }
}

__global__ void __launch_bounds__(NTHREADS, 1)
fused_message_kernel(
    const float* __restrict__ s_g, const float* __restrict__ r_g,
    const float* __restrict__ v_g, const int*   __restrict__ idx_g,
    const float* __restrict__ Wp_g, const float* __restrict__ bphi_g,
    const float* __restrict__ Ww_g, const float* __restrict__ bw_g,
    float* __restrict__ out_v, float* __restrict__ out_s, int E)
{
  extern __shared__ float sm[];
  float* s_sm  = sm;                   // [64][SROW]
  float* ov_sm = sm + TM*SROW;         // overlay: prologue rbf+Ww, mainloop W_phi half [64][384]
  float* w_sm  = ov_sm + 24576;        // [64][384]
  float* rn_sm = w_sm + 24576;         // [64][3]
  int*  idx_sm = (int*)(rn_sm + TM*3); // [64]

  const int tid = threadIdx.x;
  const int tx  = tid & 15;   // feature group: owns n = {tx*4..+3} and {64+tx*4..+3} per chunk
  const int ty  = tid >> 4;   // edge group:    owns edges ty*4..ty*4+3
  const int eb  = blockIdx.x * TM;

  float* rbfO = ov_sm;             // [64][NRBF]
  float* WwO  = ov_sm + TM*NRBF;   // [20][384]

  // ---------------- prologue: rbf / rn / idx / Ww / s tile ----------------
  if (tid < TM){
    int e = eb + tid;
    if (e < E){
      float rx = r_g[3*e+0], ry = r_g[3*e+1], rz = r_g[3*e+2];
      float rn = sqrtf(fmaf(rx,rx, fmaf(ry,ry, rz*rz)));
      float invg = rsqrtf(g_sum);                 // global Frobenius norm of r
      rn_sm[tid*3+0] = rx*invg;
      rn_sm[tid*3+1] = ry*invg;
      rn_sm[tid*3+2] = rz*invg;
      idx_sm[tid] = idx_g[e];
      float inv_rn = 1.f/rn;
      const float c0 = 0.62831853071795864769f;   // pi / R_CUT
      #pragma unroll
      for (int k = 0; k < NRBF; k++){
        float t = sinf((float)(k+1) * c0 * rn) * inv_rn;
        rbfO[tid*NRBF + k] = (t <= 5.0f) ? 0.5f*(cosf(c0*t) + 1.f) : 0.f;
      }
    } else {
      rn_sm[tid*3+0]=0.f; rn_sm[tid*3+1]=0.f; rn_sm[tid*3+2]=0.f;
      idx_sm[tid]=0;
      #pragma unroll
      for (int k = 0; k < NRBF; k++) rbfO[tid*NRBF+k] = 0.f;
    }
  }
  for (int i = tid; i < NRBF*3*F; i += NTHREADS) WwO[i] = Ww_g[i];
  {
    const int lane = tid & 31, wrp = tid >> 5;
    const float4* s4 = (const float4*)s_g;
    #pragma unroll
    for (int j = 0; j < 8; j++){
      int el = wrp*8 + j;
      int e  = eb + el;
      float4 val = make_float4(0.f,0.f,0.f,0.f);
      if (e < E) val = s4[(size_t)e*(F/4) + lane];
      *((float4*)(s_sm + el*SROW) + lane) = val;
    }
  }
  __syncthreads();

  // ---------------- w tile: w = rbf @ W_w + b_w  (packed f32x2) ----------------
  {
    #pragma unroll
    for (int c = 0; c < 3; c++){
      unsigned long long wacc[4][2][2];
      {
        const float4 b0 = *(const float4*)(bw_g + c*F + tx*4);
        const float4 b1 = *(const float4*)(bw_g + c*F + 64 + tx*4);
        unsigned long long i00 = pack2f(b0.x,b0.y), i01 = pack2f(b0.z,b0.w);
        unsigned long long i10 = pack2f(b1.x,b1.y), i11 = pack2f(b1.z,b1.w);
        #pragma unroll
        for (int i = 0; i < 4; i++){
          wacc[i][0][0]=i00; wacc[i][0][1]=i01; wacc[i][1][0]=i10; wacc[i][1][1]=i11;
        }
      }
      #pragma unroll
      for (int k = 0; k < NRBF; k++){
        unsigned long long rb[4];
        #pragma unroll
        for (int i = 0; i < 4; i++) rb[i] = pack2(rbfO[(ty*4+i)*NRBF + k]);
        const ulonglong2 g0 = *(const ulonglong2*)(WwO + k*3*F + c*F + tx*4);
        const ulonglong2 g1 = *(const ulonglong2*)(WwO + k*3*F + c*F + 64 + tx*4);
        #pragma unroll
        for (int i = 0; i < 4; i++){
          wacc[i][0][0] = ffma2(rb[i], g0.x, wacc[i][0][0]);
          wacc[i][0][1] = ffma2(rb[i], g0.y, wacc[i][0][1]);
          wacc[i][1][0] = ffma2(rb[i], g1.x, wacc[i][1][0]);
          wacc[i][1][1] = ffma2(rb[i], g1.y, wacc[i][1][1]);
        }
      }
      #pragma unroll
      for (int i = 0; i < 4; i++){
        ulonglong2 st0; st0.x = wacc[i][0][0]; st0.y = wacc[i][0][1];
        ulonglong2 st1; st1.x = wacc[i][1][0]; st1.y = wacc[i][1][1];
        *(ulonglong2*)(w_sm + (ty*4+i)*3*F + c*F + tx*4)      = st0;
        *(ulonglong2*)(w_sm + (ty*4+i)*3*F + c*F + 64 + tx*4) = st1;
      }
    }
  }
  __syncthreads();

  // ---------------- GEMM: phi = s @ W_phi (packed f32x2, W staged in 2 halves) ----------------
  unsigned long long acc[3][4][2][2];
  #pragma unroll
  for (int c = 0; c < 3; c++)
    #pragma unroll
    for (int i = 0; i < 4; i++)
      #pragma unroll
      for (int q = 0; q < 2; q++){ acc[c][i][q][0] = 0ULL; acc[c][i][q][1] = 0ULL; }

  #pragma unroll 1
  for (int h = 0; h < 2; h++){
    {
      const float4* W4  = (const float4*)(Wp_g + h*64*3*F);
      float4*       ov4 = (float4*)ov_sm;
      #pragma unroll
      for (int i = 0; i < 24; i++)       // 24*256*4 = 24576 floats
        ov4[i*NTHREADS + tid] = W4[i*NTHREADS + tid];
    }
    __syncthreads();
    #pragma unroll 2
    for (int kk = 0; kk < 64; kk++){
      const int k = h*64 + kk;
      unsigned long long A[4];
      #pragma unroll
      for (int i = 0; i < 4; i++) A[i] = pack2(s_sm[(ty*4+i)*SROW + k]);
      #pragma unroll
      for (int c = 0; c < 3; c++){
        const ulonglong2 g0 = *(const ulonglong2*)(ov_sm + kk*3*F + c*F + tx*4);
        const ulonglong2 g1 = *(const ulonglong2*)(ov_sm + kk*3*F + c*F + 64 + tx*4);
        #pragma unroll
        for (int i = 0; i < 4; i++){
          acc[c][i][0][0] = ffma2(A[i], g0.x, acc[c][i][0][0]);
          acc[c][i][0][1] = ffma2(A[i], g0.y, acc[c][i][0][1]);
          acc[c][i][1][0] = ffma2(A[i], g1.x, acc[c][i][1][0]);
          acc[c][i][1][1] = ffma2(A[i], g1.y, acc[c][i][1][1]);
        }
      }
    }
    __syncthreads();
  }

  // ---------------- epilogue: gate + vectorized reductions ----------------
  float4 bph[3][2];
  #pragma unroll
  for (int c = 0; c < 3; c++){
    bph[c][0] = *(const float4*)(bphi_g + c*F + tx*4);
    bph[c][1] = *(const float4*)(bphi_g + c*F + 64 + tx*4);
  }

  #pragma unroll
  for (int i = 0; i < 4; i++){
    const int el = ty*4 + i;
    const int e  = eb + el;
    if (e < E){
      const int node = idx_sm[el];
      const float rn0 = rn_sm[el*3+0], rn1 = rn_sm[el*3+1], rn2 = rn_sm[el*3+2];
      float sv[2][4], ssv[2][4], sr[2][4];
      #pragma unroll
      for (int c = 0; c < 3; c++){
        #pragma unroll
        for (int q = 0; q < 2; q++){
          const float4 wq = *(const float4*)(w_sm + el*3*F + c*F + q*64 + tx*4);
          float lo0, hi0, lo1, hi1;
          unpack2(acc[c][i][q][0], lo0, hi0);
          unpack2(acc[c][i][q][1], lo1, hi1);
          const float4 bq = bph[c][q];
          float o0 = wq.x * (lo0 + bq.x);
          float o1 = wq.y * (hi0 + bq.y);
          float o2 = wq.z * (lo1 + bq.z);
          float o3 = wq.w * (hi1 + bq.w);
          float* dst = (c==0) ? sv[q] : (c==1) ? ssv[q] : sr[q];
          dst[0]=o0; dst[1]=o1; dst[2]=o2; dst[3]=o3;
        }
      }
      // out_s += ss
      float* osp = out_s + (size_t)node*F + tx*4;
      red4(osp,      ssv[0][0], ssv[0][1], ssv[0][2], ssv[0][3]);
      red4(osp + 64, ssv[1][0], ssv[1][1], ssv[1][2], ssv[1][3]);
      // out_v += sv*v + sr*rn[d]
      const float* vp  = v_g  + (size_t)e*3*F    + tx*4;
      float*       ovp = out_v + (size_t)node*3*F + tx*4;
      #pragma unroll
      for (int d = 0; d < 3; d++){
        const float rnd = (d==0) ? rn0 : (d==1) ? rn1 : rn2;
        #pragma unroll
        for (int q = 0; q < 2; q++){
          const float4 vv = *(const float4*)(vp + d*F + q*64);
          float m0 = fmaf(sv[q][0], vv.x, sr[q][0]*rnd);
          float m1 = fmaf(sv[q][1], vv.y, sr[q][1]*rnd);
          float m2 = fmaf(sv[q][2], vv.z, sr[q][2]*rnd);
          float m3 = fmaf(sv[q][3], vv.w, sr[q][3]*rnd);
          red4(ovp + d*F + q*64, m0, m1, m2, m3);
        }
      }
    }
  }
}

extern "C" void kernel_launch(void* const* d_in, const int* in_sizes, int n_in,
                              void* d_out, int out_size){
  const float* s_g  = (const float*)d_in[0];
  const float* r_g  = (const float*)d_in[1];
  const float* v_g  = (const float*)d_in[2];
  const int*   idx  = (const int*)  d_in[3];
  const float* Wp   = (const float*)d_in[4];
  const float* bphi = (const float*)d_in[5];
  const float* Ww   = (const float*)d_in[6];
  const float* bw   = (const float*)d_in[7];
  const int E = in_sizes[1] / 3;            // r is (E,3)
  const int N = out_size / (4*F);           // out = out_v (N*3*F) ++ out_s (N*F)
  float* out_v = (float*)d_out;
  float* out_s = out_v + (size_t)N*3*F;

  cudaMemsetAsync(d_out, 0, (size_t)out_size * sizeof(float));
  zero_gsum_kernel<<<1,1>>>();
  reduce_sumsq_kernel<<<512, 256>>>(r_g, 3*E);
  cudaFuncSetAttribute(fused_message_kernel,
                       cudaFuncAttributeMaxDynamicSharedMemorySize, SMEM_BYTES);
  const int blocks = (E + TM - 1) / TM;
  fused_message_kernel<<<blocks, NTHREADS, SMEM_BYTES>>>(
      s_g, r_g, v_g, idx, Wp, bphi, Ww, bw, out_v, out_s, E);
}